// round 11
// baseline (speedup 1.0000x reference)
#include <cuda_runtime.h>
#include <math.h>

#define BB 8
#define NN 2048
#define NP (BB*NN)      // 16384 points
#define DD 64
#define KK 8
#define LL 3
#define H1 256
#define H2 128

// ---- scratch (device globals; no allocation allowed) ----
__device__ float g_fw[NP*LL];         // 192 KB
__device__ int   g_idx[NP*KK];        // 512 KB
__device__ float g_fcfn[NP*2*DD];     // 8 MB
__device__ float g_agg[NP*DD];        // 4 MB
__device__ float g_pd[NP*4*KK];       // 2 MB
__device__ int   g_pi[NP*4*KK];       // 2 MB

__device__ __forceinline__ float leaky_f(float v) { return v > 0.f ? v : 0.2f*v; }

// ---- tf32 helpers ----
__device__ __forceinline__ unsigned int f2t(float f) {
    unsigned int u;
    asm("cvt.rna.tf32.f32 %0, %1;" : "=r"(u) : "f"(f));
    return u;
}
__device__ __forceinline__ void mma8(float* c,
    unsigned a0, unsigned a1, unsigned a2, unsigned a3,
    unsigned b0, unsigned b1)
{
    asm("mma.sync.aligned.m16n8k8.row.col.f32.tf32.tf32.f32 "
        "{%0,%1,%2,%3}, {%4,%5,%6,%7}, {%8,%9}, {%0,%1,%2,%3};"
        : "+f"(c[0]), "+f"(c[1]), "+f"(c[2]), "+f"(c[3])
        : "r"(a0), "r"(a1), "r"(a2), "r"(a3), "r"(b0), "r"(b1));
}

// ============================================================
// Kernel 1+3 fused: feat -> [fc|fn] via tf32 mma, plus fw.
// 64 pts/block, 256 thr (quad per point for feat), grid 256.
// feat never touches gmem: computed straight into smem A-tile.
// ============================================================
#define FC_FP 76
#define FC_WP 136
__global__ __launch_bounds__(256)
void k_featfc(const float* __restrict__ x,
              const float* __restrict__ W1, const float* __restrict__ b1,
              const float* __restrict__ g1, const float* __restrict__ be1,
              const float* __restrict__ Ws1, const float* __restrict__ bs1,
              const float* __restrict__ Ws2, const float* __restrict__ bs2,
              const float* __restrict__ W2)
{
    __shared__ float fs[64*FC_FP];   // 19.5 KB (feat tile, tf32)
    __shared__ float ws[64*FC_WP];   // 34.8 KB (W2cat, tf32)
    int tid = threadIdx.x;
    int pb  = blockIdx.x * 64;

    // ---- Phase 1: feat + suppressor. 4 threads/point, 16 dims each. ----
    {
        int pl = tid >> 2;          // local point 0..63
        int q  = tid & 3;           // quad lane
        int p  = pb + pl;
        float x0 = x[p*3+0], x1 = x[p*3+1], x2 = x[p*3+2];

        float a0 = 0.f, a1 = 0.f, a2 = 0.f;
        #pragma unroll
        for (int i = 0; i < 16; ++i) {
            int d = q*16 + i;
            float v = fmaf(x2, W1[128+d], fmaf(x1, W1[64+d], fmaf(x0, W1[d], b1[d])));
            v = v * g1[d] + be1[d];
            fs[pl*FC_FP + d] = __uint_as_float(f2t(leaky_f(v)));

            float hv = fmaf(x2, Ws1[128+d], fmaf(x1, Ws1[64+d], fmaf(x0, Ws1[d], bs1[d])));
            hv = hv > 0.f ? hv : 0.f;
            a0 = fmaf(hv, Ws2[d*3+0], a0);
            a1 = fmaf(hv, Ws2[d*3+1], a1);
            a2 = fmaf(hv, Ws2[d*3+2], a2);
        }
        // quad reduce (lanes q^1, q^2 stay inside the quad)
        a0 += __shfl_xor_sync(0xFFFFFFFF, a0, 1);
        a1 += __shfl_xor_sync(0xFFFFFFFF, a1, 1);
        a2 += __shfl_xor_sync(0xFFFFFFFF, a2, 1);
        a0 += __shfl_xor_sync(0xFFFFFFFF, a0, 2);
        a1 += __shfl_xor_sync(0xFFFFFFFF, a1, 2);
        a2 += __shfl_xor_sync(0xFFFFFFFF, a2, 2);
        if (q == 0) {
            g_fw[p*3+0] = 1.f/(1.f + expf(-a0));
            g_fw[p*3+1] = 1.f/(1.f + expf(-a1));
            g_fw[p*3+2] = 1.f/(1.f + expf(-a2));
        }
    }

    // ---- Phase 2: stage W2cat [c][j] tf32 ----
    for (int i = tid; i < 64*32; i += 256) {
        int c = i >> 5, jf = i & 31;
        float4 v = (jf < 16)
            ? *(const float4*)&W2[c*64 + jf*4]
            : *(const float4*)&W2[(64+c)*64 + (jf-16)*4];
        int j0 = jf * 4;
        ws[c*FC_WP + j0+0] = __uint_as_float(f2t(v.x));
        ws[c*FC_WP + j0+1] = __uint_as_float(f2t(v.y));
        ws[c*FC_WP + j0+2] = __uint_as_float(f2t(v.z));
        ws[c*FC_WP + j0+3] = __uint_as_float(f2t(v.w));
    }
    __syncthreads();

    // ---- Phase 3: mma (identical to validated k_fcfn v4) ----
    int wid = tid >> 5, lane = tid & 31;
    int g = lane >> 2, t = lane & 3;
    int m0 = (wid >> 1) * 16;
    int nh = wid & 1;

    float acc[8][4];
    #pragma unroll
    for (int q2 = 0; q2 < 8; ++q2)
        #pragma unroll
        for (int r = 0; r < 4; ++r) acc[q2][r] = 0.f;

    #pragma unroll
    for (int r8 = 0; r8 < 8; ++r8) {
        int k0 = r8 * 8;
        unsigned a0 = __float_as_uint(fs[(m0+g)*FC_FP + k0+t]);
        unsigned a1 = __float_as_uint(fs[(m0+g+8)*FC_FP + k0+t]);
        unsigned a2 = __float_as_uint(fs[(m0+g)*FC_FP + k0+t+4]);
        unsigned a3 = __float_as_uint(fs[(m0+g+8)*FC_FP + k0+t+4]);
        #pragma unroll
        for (int nt = 0; nt < 8; ++nt) {
            int n = nh*64 + nt*8 + g;
            unsigned b0 = __float_as_uint(ws[(k0+t)*FC_WP + n]);
            unsigned b1 = __float_as_uint(ws[(k0+t+4)*FC_WP + n]);
            mma8(acc[nt], a0, a1, a2, a3, b0, b1);
        }
    }

    #pragma unroll
    for (int nt = 0; nt < 8; ++nt) {
        int j = nh*64 + nt*8 + 2*t;
        *(float2*)&g_fcfn[(size_t)(pb+m0+g)*128 + j]   = make_float2(acc[nt][0], acc[nt][1]);
        *(float2*)&g_fcfn[(size_t)(pb+m0+g+8)*128 + j] = make_float2(acc[nt][2], acc[nt][3]);
    }
}

// ============================================================
// Kernel 2a: KNN partial — 4 slices of 512 (unchanged)
// ============================================================
__global__ __launch_bounds__(128)
void k_knn_part(const float* __restrict__ x)
{
    __shared__ float4 xs[512];
    int tid = threadIdx.x;
    int s   = blockIdx.x & 3;
    int t   = (blockIdx.x >> 2) & 15;
    int b   = blockIdx.x >> 6;
    const float* xb = x + (size_t)b * NN * 3;
    int m0 = s * 512;

    for (int i = tid; i < 512; i += 128) {
        int m = m0 + i;
        float a0 = xb[m*3+0], a1 = xb[m*3+1], a2 = xb[m*3+2];
        xs[i] = make_float4(a0, a1, a2, a0*a0 + a1*a1 + a2*a2);
    }
    __syncthreads();

    int n = t*128 + tid;
    float c0 = xb[n*3+0], c1 = xb[n*3+1], c2 = xb[n*3+2];
    float cw = c0*c0 + c1*c1 + c2*c2;

    float bd[KK]; int bi[KK];
    #pragma unroll
    for (int k = 0; k < KK; ++k) { bd[k] = 3.4e38f; bi[k] = 0; }

    #pragma unroll 4
    for (int i = 0; i < 512; ++i) {
        float4 q = xs[i];
        float d2 = cw + q.w - 2.f*(c0*q.x + c1*q.y + c2*q.z);
        if (d2 < bd[KK-1]) {
            float v = d2; int vi = m0 + i;
            #pragma unroll
            for (int k = 0; k < KK; ++k) {
                if (v < bd[k]) {
                    float td = bd[k]; int ti = bi[k];
                    bd[k] = v; bi[k] = vi; v = td; vi = ti;
                }
            }
        }
    }
    int p = b*NN + n;
    #pragma unroll
    for (int k = 0; k < KK; ++k) {
        g_pd[(size_t)(s*KK + k)*NP + p] = bd[k];
        g_pi[(size_t)(s*KK + k)*NP + p] = bi[k];
    }
}

// ============================================================
// Kernel 2b: KNN merge (unchanged)
// ============================================================
__global__ __launch_bounds__(256)
void k_knn_merge()
{
    int p = blockIdx.x * 256 + threadIdx.x;
    float bd[KK]; int bi[KK];
    #pragma unroll
    for (int k = 0; k < KK; ++k) { bd[k] = 3.4e38f; bi[k] = 0; }

    #pragma unroll
    for (int s = 0; s < 4; ++s) {
        #pragma unroll
        for (int k2 = 0; k2 < KK; ++k2) {
            float v  = g_pd[(size_t)(s*KK + k2)*NP + p];
            int   vi = g_pi[(size_t)(s*KK + k2)*NP + p];
            if (v < bd[KK-1]) {
                #pragma unroll
                for (int k = 0; k < KK; ++k) {
                    if (v < bd[k]) {
                        float td = bd[k]; int ti = bi[k];
                        bd[k] = v; bi[k] = vi; v = td; vi = ti;
                    }
                }
            }
        }
    }
    #pragma unroll
    for (int k = 0; k < KK; ++k) g_idx[(size_t)p*KK + k] = bi[k];
}

// ============================================================
// Kernel 4: edge conv + max-agg (unchanged)
// ============================================================
__global__ __launch_bounds__(256)
void k_edge(const float* __restrict__ b2,
            const float* __restrict__ g2,
            const float* __restrict__ be2)
{
    int g = blockIdx.x * 256 + threadIdx.x;
    int p = g >> 4, d4 = (g & 15) * 4;
    int b = p >> 11;

    float4 fc = *(const float4*)&g_fcfn[(size_t)p*128 + d4];
    float4 Bv = *(const float4*)&b2[d4];
    float4 Gv = *(const float4*)&g2[d4];
    float4 Ev = *(const float4*)&be2[d4];
    float bx = fc.x + Bv.x, by = fc.y + Bv.y, bz = fc.z + Bv.z, bw = fc.w + Bv.w;

    int m[KK];
    const int* ip = g_idx + (size_t)p*KK;
    #pragma unroll
    for (int k = 0; k < KK; ++k) m[k] = ip[k];

    size_t rowb = (size_t)(b << 11) * 128 + 64 + d4;
    float mx0 = -3.4e38f, mx1 = -3.4e38f, mx2 = -3.4e38f, mx3 = -3.4e38f;
    #pragma unroll
    for (int k = 0; k < KK; ++k) {
        float4 fn = *(const float4*)&g_fcfn[rowb + (size_t)m[k]*128];
        mx0 = fmaxf(mx0, leaky_f((bx + fn.x) * Gv.x + Ev.x));
        mx1 = fmaxf(mx1, leaky_f((by + fn.y) * Gv.y + Ev.y));
        mx2 = fmaxf(mx2, leaky_f((bz + fn.z) * Gv.z + Ev.z));
        mx3 = fmaxf(mx3, leaky_f((bw + fn.w) * Gv.w + Ev.w));
    }
    *(float4*)&g_agg[(size_t)p*DD + d4] = make_float4(mx0, mx1, mx2, mx3);
}

// ============================================================
// Kernel 5 v4: fusion MLP via tf32 mma, 64 pts/block, grid 256.
// Warp = (m16-tile wid>>1, n-half wid&1). Halves weight restaging.
// smem: ws [8704] | multi 64x204 (h2 64x132 overlay) | h1 64x260
// ============================================================
#define MPAD  204
#define H1PAD 260
#define H2PAD 132
#define WS1   264
#define WS2   136
#define WSF   8704
#define MOFF  WSF
#define H1OFF (WSF + 64*MPAD)
#define FUS_SMEM ((WSF + 64*MPAD + 64*H1PAD) * 4)   // 153600 B

__global__ __launch_bounds__(256)
void k_fusion(const float* __restrict__ x,
              const float* __restrict__ Wf1, const float* __restrict__ bf1,
              const float* __restrict__ gf1, const float* __restrict__ bef1,
              const float* __restrict__ Wf2, const float* __restrict__ bf2,
              const float* __restrict__ gf2, const float* __restrict__ bef2,
              const float* __restrict__ Wf3, const float* __restrict__ bf3,
              float* __restrict__ out)
{
    extern __shared__ __align__(16) float smem[];
    float* ws    = smem;
    float* multi = smem + MOFF;
    float* h2_s  = multi;             // overlay (multi dead after layer 1)
    float* h1_s  = smem + H1OFF;

    int tid  = threadIdx.x;
    int pb   = blockIdx.x * 64;
    int wid  = tid >> 5, lane = tid & 31;
    int g    = lane >> 2, t = lane & 3;
    int m0   = (wid >> 1) * 16;       // 4 m-tiles cover 64 points
    int nh   = wid & 1;               // n-half

    // Phase A: multi[p][kk] = agg[p][kk&63]*fw[p][kk>>6], tf32-rounded
    for (int i = tid; i < 64*192; i += 256) {
        int p = i / 192, kk = i - p*192;
        float v = g_agg[(size_t)(pb+p)*DD + (kk & 63)]
                * g_fw[(size_t)(pb+p)*3 + (kk >> 6)];
        multi[p*MPAD + kk] = __uint_as_float(f2t(v));
    }

    // ---- Layer 1: h1 = leaky(BN(multi @ Wf1)), M64 N256 K192 ----
    {
        float c1r[16][4];
        #pragma unroll
        for (int q = 0; q < 16; ++q)
            #pragma unroll
            for (int r = 0; r < 4; ++r) c1r[q][r] = 0.f;

        for (int kc = 0; kc < 192; kc += 32) {
            __syncthreads();
            for (int i = tid; i < 2048; i += 256) {
                int r = i >> 6, c4 = (i & 63) * 4;
                float4 wv = *(const float4*)&Wf1[(kc+r)*256 + c4];
                ws[r*WS1 + c4+0] = __uint_as_float(f2t(wv.x));
                ws[r*WS1 + c4+1] = __uint_as_float(f2t(wv.y));
                ws[r*WS1 + c4+2] = __uint_as_float(f2t(wv.z));
                ws[r*WS1 + c4+3] = __uint_as_float(f2t(wv.w));
            }
            __syncthreads();

            #pragma unroll
            for (int r8 = 0; r8 < 4; ++r8) {
                int k0 = r8 * 8;
                int cA = kc + k0 + t;
                unsigned a0 = __float_as_uint(multi[(m0+g)*MPAD + cA]);
                unsigned a1 = __float_as_uint(multi[(m0+g+8)*MPAD + cA]);
                unsigned a2 = __float_as_uint(multi[(m0+g)*MPAD + cA+4]);
                unsigned a3 = __float_as_uint(multi[(m0+g+8)*MPAD + cA+4]);
                #pragma unroll
                for (int nt = 0; nt < 16; ++nt) {
                    int n = nh*128 + nt*8 + g;
                    unsigned b0 = __float_as_uint(ws[(k0+t)*WS1 + n]);
                    unsigned b1 = __float_as_uint(ws[(k0+t+4)*WS1 + n]);
                    mma8(c1r[nt], a0, a1, a2, a3, b0, b1);
                }
            }
        }

        #pragma unroll
        for (int nt = 0; nt < 16; ++nt) {
            int j = nh*128 + nt*8 + 2*t;
            float b_0 = bf1[j],   g_0 = gf1[j],   e_0 = bef1[j];
            float b_1 = bf1[j+1], g_1 = gf1[j+1], e_1 = bef1[j+1];
            h1_s[(m0+g)*H1PAD + j]     = __uint_as_float(f2t(leaky_f((c1r[nt][0]+b_0)*g_0+e_0)));
            h1_s[(m0+g)*H1PAD + j+1]   = __uint_as_float(f2t(leaky_f((c1r[nt][1]+b_1)*g_1+e_1)));
            h1_s[(m0+g+8)*H1PAD + j]   = __uint_as_float(f2t(leaky_f((c1r[nt][2]+b_0)*g_0+e_0)));
            h1_s[(m0+g+8)*H1PAD + j+1] = __uint_as_float(f2t(leaky_f((c1r[nt][3]+b_1)*g_1+e_1)));
        }
    }

    // ---- Layer 2: h2 = leaky(BN(h1 @ Wf2)), M64 N128 K256 ----
    {
        float c2r[8][4];
        #pragma unroll
        for (int q = 0; q < 8; ++q)
            #pragma unroll
            for (int r = 0; r < 4; ++r) c2r[q][r] = 0.f;

        for (int kc = 0; kc < 256; kc += 64) {
            __syncthreads();
            for (int i = tid; i < 2048; i += 256) {
                int r = i >> 5, c4 = (i & 31) * 4;
                float4 wv = *(const float4*)&Wf2[(kc+r)*128 + c4];
                ws[r*WS2 + c4+0] = __uint_as_float(f2t(wv.x));
                ws[r*WS2 + c4+1] = __uint_as_float(f2t(wv.y));
                ws[r*WS2 + c4+2] = __uint_as_float(f2t(wv.z));
                ws[r*WS2 + c4+3] = __uint_as_float(f2t(wv.w));
            }
            __syncthreads();

            #pragma unroll
            for (int r8 = 0; r8 < 8; ++r8) {
                int k0 = r8 * 8;
                int cA = kc + k0 + t;
                unsigned a0 = __float_as_uint(h1_s[(m0+g)*H1PAD + cA]);
                unsigned a1 = __float_as_uint(h1_s[(m0+g+8)*H1PAD + cA]);
                unsigned a2 = __float_as_uint(h1_s[(m0+g)*H1PAD + cA+4]);
                unsigned a3 = __float_as_uint(h1_s[(m0+g+8)*H1PAD + cA+4]);
                #pragma unroll
                for (int nt = 0; nt < 8; ++nt) {
                    int n = nh*64 + nt*8 + g;
                    unsigned b0 = __float_as_uint(ws[(k0+t)*WS2 + n]);
                    unsigned b1 = __float_as_uint(ws[(k0+t+4)*WS2 + n]);
                    mma8(c2r[nt], a0, a1, a2, a3, b0, b1);
                }
            }
        }

        #pragma unroll
        for (int nt = 0; nt < 8; ++nt) {
            int j = nh*64 + nt*8 + 2*t;
            float b_0 = bf2[j],   g_0 = gf2[j],   e_0 = bef2[j];
            float b_1 = bf2[j+1], g_1 = gf2[j+1], e_1 = bef2[j+1];
            h2_s[(m0+g)*H2PAD + j]     = leaky_f((c2r[nt][0]+b_0)*g_0+e_0);
            h2_s[(m0+g)*H2PAD + j+1]   = leaky_f((c2r[nt][1]+b_1)*g_1+e_1);
            h2_s[(m0+g+8)*H2PAD + j]   = leaky_f((c2r[nt][2]+b_0)*g_0+e_0);
            h2_s[(m0+g+8)*H2PAD + j+1] = leaky_f((c2r[nt][3]+b_1)*g_1+e_1);
        }
    }
    __syncthreads();

    // ---- Layer 3 + residual (192 outputs, fp32) ----
    if (tid < 64*3) {
        int p = tid / 3, c = tid - p*3;
        float acc = 0.f;
        #pragma unroll 4
        for (int kk = 0; kk < 128; ++kk)
            acc = fmaf(h2_s[p*H2PAD + kk], Wf3[kk*3 + c], acc);
        size_t o = (size_t)(pb+p)*3 + c;
        out[o] = x[o] + 0.1f * (acc + bf3[c]);
    }
}

// ============================================================
extern "C" void kernel_launch(void* const* d_in, const int* in_sizes, int n_in,
                              void* d_out, int out_size)
{
    const float* x   = (const float*)d_in[0];
    const float* W1  = (const float*)d_in[1];
    const float* b1  = (const float*)d_in[2];
    const float* g1  = (const float*)d_in[3];
    const float* be1 = (const float*)d_in[4];
    const float* W2  = (const float*)d_in[5];
    const float* b2  = (const float*)d_in[6];
    const float* g2  = (const float*)d_in[7];
    const float* be2 = (const float*)d_in[8];
    const float* Ws1 = (const float*)d_in[9];
    const float* bs1 = (const float*)d_in[10];
    const float* Ws2 = (const float*)d_in[11];
    const float* bs2 = (const float*)d_in[12];
    const float* Wf1 = (const float*)d_in[13];
    const float* bf1 = (const float*)d_in[14];
    const float* gf1 = (const float*)d_in[15];
    const float* bef1= (const float*)d_in[16];
    const float* Wf2 = (const float*)d_in[17];
    const float* bf2 = (const float*)d_in[18];
    const float* gf2 = (const float*)d_in[19];
    const float* bef2= (const float*)d_in[20];
    const float* Wf3 = (const float*)d_in[21];
    const float* bf3 = (const float*)d_in[22];
    float* out = (float*)d_out;

    cudaFuncSetAttribute(k_fusion, cudaFuncAttributeMaxDynamicSharedMemorySize,
                         FUS_SMEM);

    k_featfc<<<NP/64, 256>>>(x, W1, b1, g1, be1, Ws1, bs1, Ws2, bs2, W2);
    k_knn_part<<<BB*16*4, 128>>>(x);
    k_knn_merge<<<NP/256, 256>>>();
    k_edge<<<(NP*16)/256, 256>>>(b2, g2, be2);
    k_fusion<<<NP/64, 256, FUS_SMEM>>>(x, Wf1, bf1, gf1, bef1,
                                       Wf2, bf2, gf2, bef2, Wf3, bf3, out);
}

// round 13
// speedup vs baseline: 1.0650x; 1.0650x over previous
#include <cuda_runtime.h>
#include <math.h>

#define BB 8
#define NN 2048
#define NP (BB*NN)      // 16384 points
#define DD 64
#define KK 8
#define LL 3
#define H1 256
#define H2 128

// ---- scratch (device globals; no allocation allowed) ----
__device__ float g_fw[NP*LL];         // 192 KB
__device__ int   g_idx[NP*KK];        // 512 KB
__device__ float g_fcfn[NP*2*DD];     // 8 MB
__device__ float g_agg[NP*DD];        // 4 MB
__device__ float g_pd[NP*4*KK];       // 2 MB
__device__ int   g_pi[NP*4*KK];       // 2 MB

__device__ __forceinline__ float leaky_f(float v) { return v > 0.f ? v : 0.2f*v; }

// ---- tf32 helpers ----
__device__ __forceinline__ unsigned int f2t(float f) {
    unsigned int u;
    asm("cvt.rna.tf32.f32 %0, %1;" : "=r"(u) : "f"(f));
    return u;
}
__device__ __forceinline__ void mma8(float* c,
    unsigned a0, unsigned a1, unsigned a2, unsigned a3,
    unsigned b0, unsigned b1)
{
    asm("mma.sync.aligned.m16n8k8.row.col.f32.tf32.tf32.f32 "
        "{%0,%1,%2,%3}, {%4,%5,%6,%7}, {%8,%9}, {%0,%1,%2,%3};"
        : "+f"(c[0]), "+f"(c[1]), "+f"(c[2]), "+f"(c[3])
        : "r"(a0), "r"(a1), "r"(a2), "r"(a3), "r"(b0), "r"(b1));
}

// ============================================================
// Kernel 1+3 fused: feat -> [fc|fn] via tf32 mma, plus fw.
// 64 pts/block, 256 thr (quad per point for feat), grid 256.
// ============================================================
#define FC_FP 76
#define FC_WP 136
__global__ __launch_bounds__(256)
void k_featfc(const float* __restrict__ x,
              const float* __restrict__ W1, const float* __restrict__ b1,
              const float* __restrict__ g1, const float* __restrict__ be1,
              const float* __restrict__ Ws1, const float* __restrict__ bs1,
              const float* __restrict__ Ws2, const float* __restrict__ bs2,
              const float* __restrict__ W2)
{
    __shared__ float fs[64*FC_FP];   // 19.5 KB (feat tile, tf32)
    __shared__ float ws[64*FC_WP];   // 34.8 KB (W2cat, tf32)
    int tid = threadIdx.x;
    int pb  = blockIdx.x * 64;

    // ---- Phase 1: feat + suppressor. 4 threads/point, 16 dims each. ----
    {
        int pl = tid >> 2;          // local point 0..63
        int q  = tid & 3;           // quad lane
        int p  = pb + pl;
        float x0 = x[p*3+0], x1 = x[p*3+1], x2 = x[p*3+2];

        float a0 = 0.f, a1 = 0.f, a2 = 0.f;
        #pragma unroll
        for (int i = 0; i < 16; ++i) {
            int d = q*16 + i;
            float v = fmaf(x2, W1[128+d], fmaf(x1, W1[64+d], fmaf(x0, W1[d], b1[d])));
            v = v * g1[d] + be1[d];
            fs[pl*FC_FP + d] = __uint_as_float(f2t(leaky_f(v)));

            float hv = fmaf(x2, Ws1[128+d], fmaf(x1, Ws1[64+d], fmaf(x0, Ws1[d], bs1[d])));
            hv = hv > 0.f ? hv : 0.f;
            a0 = fmaf(hv, Ws2[d*3+0], a0);
            a1 = fmaf(hv, Ws2[d*3+1], a1);
            a2 = fmaf(hv, Ws2[d*3+2], a2);
        }
        // quad reduce
        a0 += __shfl_xor_sync(0xFFFFFFFF, a0, 1);
        a1 += __shfl_xor_sync(0xFFFFFFFF, a1, 1);
        a2 += __shfl_xor_sync(0xFFFFFFFF, a2, 1);
        a0 += __shfl_xor_sync(0xFFFFFFFF, a0, 2);
        a1 += __shfl_xor_sync(0xFFFFFFFF, a1, 2);
        a2 += __shfl_xor_sync(0xFFFFFFFF, a2, 2);
        if (q == 0) {
            g_fw[p*3+0] = 1.f/(1.f + expf(-a0));
            g_fw[p*3+1] = 1.f/(1.f + expf(-a1));
            g_fw[p*3+2] = 1.f/(1.f + expf(-a2));
        }
    }

    // ---- Phase 2: stage W2cat [c][j] tf32 ----
    for (int i = tid; i < 64*32; i += 256) {
        int c = i >> 5, jf = i & 31;
        float4 v = (jf < 16)
            ? *(const float4*)&W2[c*64 + jf*4]
            : *(const float4*)&W2[(64+c)*64 + (jf-16)*4];
        int j0 = jf * 4;
        ws[c*FC_WP + j0+0] = __uint_as_float(f2t(v.x));
        ws[c*FC_WP + j0+1] = __uint_as_float(f2t(v.y));
        ws[c*FC_WP + j0+2] = __uint_as_float(f2t(v.z));
        ws[c*FC_WP + j0+3] = __uint_as_float(f2t(v.w));
    }
    __syncthreads();

    // ---- Phase 3: mma ----
    int wid = tid >> 5, lane = tid & 31;
    int g = lane >> 2, t = lane & 3;
    int m0 = (wid >> 1) * 16;
    int nh = wid & 1;

    float acc[8][4];
    #pragma unroll
    for (int q2 = 0; q2 < 8; ++q2)
        #pragma unroll
        for (int r = 0; r < 4; ++r) acc[q2][r] = 0.f;

    #pragma unroll
    for (int r8 = 0; r8 < 8; ++r8) {
        int k0 = r8 * 8;
        unsigned a0 = __float_as_uint(fs[(m0+g)*FC_FP + k0+t]);
        unsigned a1 = __float_as_uint(fs[(m0+g+8)*FC_FP + k0+t]);
        unsigned a2 = __float_as_uint(fs[(m0+g)*FC_FP + k0+t+4]);
        unsigned a3 = __float_as_uint(fs[(m0+g+8)*FC_FP + k0+t+4]);
        #pragma unroll
        for (int nt = 0; nt < 8; ++nt) {
            int n = nh*64 + nt*8 + g;
            unsigned b0 = __float_as_uint(ws[(k0+t)*FC_WP + n]);
            unsigned b1 = __float_as_uint(ws[(k0+t+4)*FC_WP + n]);
            mma8(acc[nt], a0, a1, a2, a3, b0, b1);
        }
    }

    #pragma unroll
    for (int nt = 0; nt < 8; ++nt) {
        int j = nh*64 + nt*8 + 2*t;
        *(float2*)&g_fcfn[(size_t)(pb+m0+g)*128 + j]   = make_float2(acc[nt][0], acc[nt][1]);
        *(float2*)&g_fcfn[(size_t)(pb+m0+g+8)*128 + j] = make_float2(acc[nt][2], acc[nt][3]);
    }
}

// ============================================================
// Kernel 2a: KNN partial — 4 slices of 512 (unchanged)
// ============================================================
__global__ __launch_bounds__(128)
void k_knn_part(const float* __restrict__ x)
{
    __shared__ float4 xs[512];
    int tid = threadIdx.x;
    int s   = blockIdx.x & 3;
    int t   = (blockIdx.x >> 2) & 15;
    int b   = blockIdx.x >> 6;
    const float* xb = x + (size_t)b * NN * 3;
    int m0 = s * 512;

    for (int i = tid; i < 512; i += 128) {
        int m = m0 + i;
        float a0 = xb[m*3+0], a1 = xb[m*3+1], a2 = xb[m*3+2];
        xs[i] = make_float4(a0, a1, a2, a0*a0 + a1*a1 + a2*a2);
    }
    __syncthreads();

    int n = t*128 + tid;
    float c0 = xb[n*3+0], c1 = xb[n*3+1], c2 = xb[n*3+2];
    float cw = c0*c0 + c1*c1 + c2*c2;

    float bd[KK]; int bi[KK];
    #pragma unroll
    for (int k = 0; k < KK; ++k) { bd[k] = 3.4e38f; bi[k] = 0; }

    #pragma unroll 4
    for (int i = 0; i < 512; ++i) {
        float4 q = xs[i];
        float d2 = cw + q.w - 2.f*(c0*q.x + c1*q.y + c2*q.z);
        if (d2 < bd[KK-1]) {
            float v = d2; int vi = m0 + i;
            #pragma unroll
            for (int k = 0; k < KK; ++k) {
                if (v < bd[k]) {
                    float td = bd[k]; int ti = bi[k];
                    bd[k] = v; bi[k] = vi; v = td; vi = ti;
                }
            }
        }
    }
    int p = b*NN + n;
    #pragma unroll
    for (int k = 0; k < KK; ++k) {
        g_pd[(size_t)(s*KK + k)*NP + p] = bd[k];
        g_pi[(size_t)(s*KK + k)*NP + p] = bi[k];
    }
}

// ============================================================
// Kernel 2b: KNN merge (unchanged)
// ============================================================
__global__ __launch_bounds__(256)
void k_knn_merge()
{
    int p = blockIdx.x * 256 + threadIdx.x;
    float bd[KK]; int bi[KK];
    #pragma unroll
    for (int k = 0; k < KK; ++k) { bd[k] = 3.4e38f; bi[k] = 0; }

    #pragma unroll
    for (int s = 0; s < 4; ++s) {
        #pragma unroll
        for (int k2 = 0; k2 < KK; ++k2) {
            float v  = g_pd[(size_t)(s*KK + k2)*NP + p];
            int   vi = g_pi[(size_t)(s*KK + k2)*NP + p];
            if (v < bd[KK-1]) {
                #pragma unroll
                for (int k = 0; k < KK; ++k) {
                    if (v < bd[k]) {
                        float td = bd[k]; int ti = bi[k];
                        bd[k] = v; bi[k] = vi; v = td; vi = ti;
                    }
                }
            }
        }
    }
    #pragma unroll
    for (int k = 0; k < KK; ++k) g_idx[(size_t)p*KK + k] = bi[k];
}

// ============================================================
// Kernel 4: edge conv + max-agg (unchanged)
// ============================================================
__global__ __launch_bounds__(256)
void k_edge(const float* __restrict__ b2,
            const float* __restrict__ g2,
            const float* __restrict__ be2)
{
    int g = blockIdx.x * 256 + threadIdx.x;
    int p = g >> 4, d4 = (g & 15) * 4;
    int b = p >> 11;

    float4 fc = *(const float4*)&g_fcfn[(size_t)p*128 + d4];
    float4 Bv = *(const float4*)&b2[d4];
    float4 Gv = *(const float4*)&g2[d4];
    float4 Ev = *(const float4*)&be2[d4];
    float bx = fc.x + Bv.x, by = fc.y + Bv.y, bz = fc.z + Bv.z, bw = fc.w + Bv.w;

    int m[KK];
    const int* ip = g_idx + (size_t)p*KK;
    #pragma unroll
    for (int k = 0; k < KK; ++k) m[k] = ip[k];

    size_t rowb = (size_t)(b << 11) * 128 + 64 + d4;
    float mx0 = -3.4e38f, mx1 = -3.4e38f, mx2 = -3.4e38f, mx3 = -3.4e38f;
    #pragma unroll
    for (int k = 0; k < KK; ++k) {
        float4 fn = *(const float4*)&g_fcfn[rowb + (size_t)m[k]*128];
        mx0 = fmaxf(mx0, leaky_f((bx + fn.x) * Gv.x + Ev.x));
        mx1 = fmaxf(mx1, leaky_f((by + fn.y) * Gv.y + Ev.y));
        mx2 = fmaxf(mx2, leaky_f((bz + fn.z) * Gv.z + Ev.z));
        mx3 = fmaxf(mx3, leaky_f((bw + fn.w) * Gv.w + Ev.w));
    }
    *(float4*)&g_agg[(size_t)p*DD + d4] = make_float4(mx0, mx1, mx2, mx3);
}

// ============================================================
// Kernel 5 v3 (R7 config): fusion MLP via tf32 mma.
// 32 pts/block, 256 thr = 8 warps, grid 512, 94208 B smem (2 CTA/SM).
// ============================================================
#define MPAD  204
#define H1PAD 260
#define H2PAD 132
#define WS1   264
#define WS2   136
#define WSF   8704
#define MOFF  WSF
#define H1OFF (WSF + 32*MPAD)
#define FUS_SMEM ((WSF + 32*MPAD + 32*H1PAD) * 4)   // 94208 B

__global__ __launch_bounds__(256)
void k_fusion(const float* __restrict__ x,
              const float* __restrict__ Wf1, const float* __restrict__ bf1,
              const float* __restrict__ gf1, const float* __restrict__ bef1,
              const float* __restrict__ Wf2, const float* __restrict__ bf2,
              const float* __restrict__ gf2, const float* __restrict__ bef2,
              const float* __restrict__ Wf3, const float* __restrict__ bf3,
              float* __restrict__ out)
{
    extern __shared__ __align__(16) float smem[];
    float* ws    = smem;
    float* multi = smem + MOFF;
    float* h2_s  = multi;             // overlay (multi dead after layer 1)
    float* h1_s  = smem + H1OFF;

    int tid  = threadIdx.x;
    int pb   = blockIdx.x * 32;
    int wid  = tid >> 5, lane = tid & 31;
    int g    = lane >> 2, t = lane & 3;
    int m0   = (wid >> 2) * 16;
    int nj   = wid & 3;

    // Phase A: multi[p][kk] = agg[p][kk&63]*fw[p][kk>>6], tf32-rounded
    for (int i = tid; i < 32*192; i += 256) {
        int p = i / 192, kk = i - p*192;
        float v = g_agg[(size_t)(pb+p)*DD + (kk & 63)]
                * g_fw[(size_t)(pb+p)*3 + (kk >> 6)];
        multi[p*MPAD + kk] = __uint_as_float(f2t(v));
    }

    // ---- Layer 1: h1 = leaky(BN(multi @ Wf1)), M32 N256 K192 ----
    {
        float c1r[8][4];
        #pragma unroll
        for (int q = 0; q < 8; ++q)
            #pragma unroll
            for (int r = 0; r < 4; ++r) c1r[q][r] = 0.f;

        for (int kc = 0; kc < 192; kc += 32) {
            __syncthreads();
            for (int i = tid; i < 2048; i += 256) {
                int r = i >> 6, c4 = (i & 63) * 4;
                float4 wv = *(const float4*)&Wf1[(kc+r)*256 + c4];
                ws[r*WS1 + c4+0] = __uint_as_float(f2t(wv.x));
                ws[r*WS1 + c4+1] = __uint_as_float(f2t(wv.y));
                ws[r*WS1 + c4+2] = __uint_as_float(f2t(wv.z));
                ws[r*WS1 + c4+3] = __uint_as_float(f2t(wv.w));
            }
            __syncthreads();

            #pragma unroll
            for (int r8 = 0; r8 < 4; ++r8) {
                int k0 = r8 * 8;
                int cA = kc + k0 + t;
                unsigned a0 = __float_as_uint(multi[(m0+g)*MPAD + cA]);
                unsigned a1 = __float_as_uint(multi[(m0+g+8)*MPAD + cA]);
                unsigned a2 = __float_as_uint(multi[(m0+g)*MPAD + cA+4]);
                unsigned a3 = __float_as_uint(multi[(m0+g+8)*MPAD + cA+4]);
                #pragma unroll
                for (int nt = 0; nt < 8; ++nt) {
                    int n = nj*64 + nt*8 + g;
                    unsigned b0 = __float_as_uint(ws[(k0+t)*WS1 + n]);
                    unsigned b1 = __float_as_uint(ws[(k0+t+4)*WS1 + n]);
                    mma8(c1r[nt], a0, a1, a2, a3, b0, b1);
                }
            }
        }

        #pragma unroll
        for (int nt = 0; nt < 8; ++nt) {
            int j = nj*64 + nt*8 + 2*t;
            float b_0 = bf1[j],   g_0 = gf1[j],   e_0 = bef1[j];
            float b_1 = bf1[j+1], g_1 = gf1[j+1], e_1 = bef1[j+1];
            h1_s[(m0+g)*H1PAD + j]     = __uint_as_float(f2t(leaky_f((c1r[nt][0]+b_0)*g_0+e_0)));
            h1_s[(m0+g)*H1PAD + j+1]   = __uint_as_float(f2t(leaky_f((c1r[nt][1]+b_1)*g_1+e_1)));
            h1_s[(m0+g+8)*H1PAD + j]   = __uint_as_float(f2t(leaky_f((c1r[nt][2]+b_0)*g_0+e_0)));
            h1_s[(m0+g+8)*H1PAD + j+1] = __uint_as_float(f2t(leaky_f((c1r[nt][3]+b_1)*g_1+e_1)));
        }
    }

    // ---- Layer 2: h2 = leaky(BN(h1 @ Wf2)), M32 N128 K256 ----
    {
        float c2r[4][4];
        #pragma unroll
        for (int q = 0; q < 4; ++q)
            #pragma unroll
            for (int r = 0; r < 4; ++r) c2r[q][r] = 0.f;

        for (int kc = 0; kc < 256; kc += 64) {
            __syncthreads();
            for (int i = tid; i < 2048; i += 256) {
                int r = i >> 5, c4 = (i & 31) * 4;
                float4 wv = *(const float4*)&Wf2[(kc+r)*128 + c4];
                ws[r*WS2 + c4+0] = __uint_as_float(f2t(wv.x));
                ws[r*WS2 + c4+1] = __uint_as_float(f2t(wv.y));
                ws[r*WS2 + c4+2] = __uint_as_float(f2t(wv.z));
                ws[r*WS2 + c4+3] = __uint_as_float(f2t(wv.w));
            }
            __syncthreads();

            #pragma unroll
            for (int r8 = 0; r8 < 8; ++r8) {
                int k0 = r8 * 8;
                int cA = kc + k0 + t;
                unsigned a0 = __float_as_uint(h1_s[(m0+g)*H1PAD + cA]);
                unsigned a1 = __float_as_uint(h1_s[(m0+g+8)*H1PAD + cA]);
                unsigned a2 = __float_as_uint(h1_s[(m0+g)*H1PAD + cA+4]);
                unsigned a3 = __float_as_uint(h1_s[(m0+g+8)*H1PAD + cA+4]);
                #pragma unroll
                for (int nt = 0; nt < 4; ++nt) {
                    int n = nj*32 + nt*8 + g;
                    unsigned b0 = __float_as_uint(ws[(k0+t)*WS2 + n]);
                    unsigned b1 = __float_as_uint(ws[(k0+t+4)*WS2 + n]);
                    mma8(c2r[nt], a0, a1, a2, a3, b0, b1);
                }
            }
        }

        #pragma unroll
        for (int nt = 0; nt < 4; ++nt) {
            int j = nj*32 + nt*8 + 2*t;
            float b_0 = bf2[j],   g_0 = gf2[j],   e_0 = bef2[j];
            float b_1 = bf2[j+1], g_1 = gf2[j+1], e_1 = bef2[j+1];
            h2_s[(m0+g)*H2PAD + j]     = leaky_f((c2r[nt][0]+b_0)*g_0+e_0);
            h2_s[(m0+g)*H2PAD + j+1]   = leaky_f((c2r[nt][1]+b_1)*g_1+e_1);
            h2_s[(m0+g+8)*H2PAD + j]   = leaky_f((c2r[nt][2]+b_0)*g_0+e_0);
            h2_s[(m0+g+8)*H2PAD + j+1] = leaky_f((c2r[nt][3]+b_1)*g_1+e_1);
        }
    }
    __syncthreads();

    // ---- Layer 3 + residual (96 outputs, fp32) ----
    if (tid < 32*3) {
        int p = tid / 3, c = tid - p*3;
        float acc = 0.f;
        #pragma unroll 4
        for (int kk = 0; kk < 128; ++kk)
            acc = fmaf(h2_s[p*H2PAD + kk], Wf3[kk*3 + c], acc);
        size_t o = (size_t)(pb+p)*3 + c;
        out[o] = x[o] + 0.1f * (acc + bf3[c]);
    }
}

// ============================================================
extern "C" void kernel_launch(void* const* d_in, const int* in_sizes, int n_in,
                              void* d_out, int out_size)
{
    const float* x   = (const float*)d_in[0];
    const float* W1  = (const float*)d_in[1];
    const float* b1  = (const float*)d_in[2];
    const float* g1  = (const float*)d_in[3];
    const float* be1 = (const float*)d_in[4];
    const float* W2  = (const float*)d_in[5];
    const float* b2  = (const float*)d_in[6];
    const float* g2  = (const float*)d_in[7];
    const float* be2 = (const float*)d_in[8];
    const float* Ws1 = (const float*)d_in[9];
    const float* bs1 = (const float*)d_in[10];
    const float* Ws2 = (const float*)d_in[11];
    const float* bs2 = (const float*)d_in[12];
    const float* Wf1 = (const float*)d_in[13];
    const float* bf1 = (const float*)d_in[14];
    const float* gf1 = (const float*)d_in[15];
    const float* bef1= (const float*)d_in[16];
    const float* Wf2 = (const float*)d_in[17];
    const float* bf2 = (const float*)d_in[18];
    const float* gf2 = (const float*)d_in[19];
    const float* bef2= (const float*)d_in[20];
    const float* Wf3 = (const float*)d_in[21];
    const float* bf3 = (const float*)d_in[22];
    float* out = (float*)d_out;

    cudaFuncSetAttribute(k_fusion, cudaFuncAttributeMaxDynamicSharedMemorySize,
                         FUS_SMEM);

    k_featfc<<<NP/64, 256>>>(x, W1, b1, g1, be1, Ws1, bs1, Ws2, bs2, W2);
    k_knn_part<<<BB*16*4, 128>>>(x);
    k_knn_merge<<<NP/256, 256>>>();
    k_edge<<<(NP*16)/256, 256>>>(b2, g2, be2);
    k_fusion<<<NP/32, 256, FUS_SMEM>>>(x, Wf1, bf1, gf1, bef1,
                                       Wf2, bf2, gf2, bef2, Wf3, bf3, out);
}